// round 8
// baseline (speedup 1.0000x reference)
#include <cuda_runtime.h>
#include <cuda_fp16.h>
#include <math.h>

#define NO 50000
#define NR 2000
#define NE 600000
#define D  128
#define NEG_SLOPE 0.2f

// ---------------- scratch ----------------
__device__ float  g_v1[D], g_v2[D], g_vd2[D];
__device__ float  g_ad1[NR], g_ad2[NR];
__device__ float2 g_as12[NO];
__device__ int    g_counts[NR];
__device__ int    g_rowptr[NR + 1];
__device__ int    g_cursor[NR];
__device__ int    g_done;
__device__ int2   g_edge[NE];          // (order_idx, edge_id) CSR order
__device__ __half g_xh[NO * D];        // fp16 x_order (raw)      12.8MB
__device__ __half g_xhr[NO * D];       // fp16 relu(x_order)      12.8MB
__device__ float  g_agg[NR * D];
__device__ float  g_r2[NR * D];

__device__ __forceinline__ float lrelu(float x) { return fmaxf(x, NEG_SLOPE * x); }

// ---------------- prep: v-vectors, ad1 rowdots, zero counters ----------------
__global__ void prep_kernel(const float* __restrict__ xr,
                            const float* __restrict__ Ws1, const float* __restrict__ as1v,
                            const float* __restrict__ Wd1, const float* __restrict__ ad1v,
                            const float* __restrict__ Ws2, const float* __restrict__ as2v,
                            const float* __restrict__ Wd2, const float* __restrict__ ad2v) {
    int b = blockIdx.x, t = threadIdx.x;  // 256 threads
    if (b < 250) {
        __shared__ __align__(16) float vd1[128];
        if (t < 128) {
            float s = 0.f;
            #pragma unroll 8
            for (int d = 0; d < 128; d++) s += Wd1[t * 128 + d] * ad1v[d];
            vd1[t] = s;
        }
        __syncthreads();
        int warp = t >> 5, lane = t & 31;
        int r = b * 8 + warp;
        float4 xv = ((const float4*)xr)[r * 32 + lane];
        float4 vv = ((const float4*)vd1)[lane];
        float s = xv.x * vv.x + xv.y * vv.y + xv.z * vv.z + xv.w * vv.w;
        #pragma unroll
        for (int o = 16; o; o >>= 1) s += __shfl_down_sync(0xffffffffu, s, o);
        if (lane == 0) g_ad1[r] = s;
    } else if (b == 253) {
        for (int i = t; i < NR; i += 256) g_counts[i] = 0;
        if (t == 0) g_done = 0;
    } else if (t < 128) {
        const float *W, *a;
        float* v;
        if (b == 250)      { W = Ws1; a = as1v; v = g_v1; }
        else if (b == 251) { W = Ws2; a = as2v; v = g_v2; }
        else               { W = Wd2; a = ad2v; v = g_vd2; }
        float s = 0.f;
        #pragma unroll 8
        for (int d = 0; d < 128; d++) s += W[t * 128 + d] * a[d];
        v[t] = s;
    }
}

// ---------------- convert (raw + relu copies) + hist + (last block) scan ----------------
#define CONV_BLKS (NO / 8)           // 6250
#define HIST_BLKS 60
#define HIST_CHUNK (NE / HIST_BLKS)  // 10000
__global__ void convert_hist_scan(const float* __restrict__ x, const int* __restrict__ ri) {
    if (blockIdx.x < CONV_BLKS) {
        int row = blockIdx.x * 8 + (threadIdx.x >> 5);
        int lane = threadIdx.x & 31;
        float4 xv = ((const float4*)x)[row * 32 + lane];
        uint2 u, ur;
        *reinterpret_cast<__half2*>(&u.x) = __floats2half2_rn(xv.x, xv.y);
        *reinterpret_cast<__half2*>(&u.y) = __floats2half2_rn(xv.z, xv.w);
        *reinterpret_cast<__half2*>(&ur.x) = __floats2half2_rn(fmaxf(xv.x, 0.f), fmaxf(xv.y, 0.f));
        *reinterpret_cast<__half2*>(&ur.y) = __floats2half2_rn(fmaxf(xv.z, 0.f), fmaxf(xv.w, 0.f));
        reinterpret_cast<uint2*>(g_xh)[row * 32 + lane] = u;
        reinterpret_cast<uint2*>(g_xhr)[row * 32 + lane] = ur;
        float4 v1 = ((const float4*)g_v1)[lane];
        float4 v2 = ((const float4*)g_v2)[lane];
        float s1 = xv.x * v1.x + xv.y * v1.y + xv.z * v1.z + xv.w * v1.w;
        float s2 = fmaxf(xv.x, 0.f) * v2.x + fmaxf(xv.y, 0.f) * v2.y +
                   fmaxf(xv.z, 0.f) * v2.z + fmaxf(xv.w, 0.f) * v2.w;
        #pragma unroll
        for (int o = 16; o; o >>= 1) {
            s1 += __shfl_down_sync(0xffffffffu, s1, o);
            s2 += __shfl_down_sync(0xffffffffu, s2, o);
        }
        if (lane == 0) g_as12[row] = make_float2(s1, s2);
        return;
    }
    // ---- histogram blocks ----
    __shared__ int sh[NR];
    int tid = threadIdx.x;
    int b = blockIdx.x - CONV_BLKS;
    int lo = b * HIST_CHUNK, hi = lo + HIST_CHUNK;
    for (int i = tid; i < NR; i += blockDim.x) sh[i] = 0;
    __syncthreads();
    for (int e = lo + tid; e < hi; e += blockDim.x) atomicAdd(&sh[ri[e]], 1);
    __syncthreads();
    for (int i = tid; i < NR; i += blockDim.x)
        if (sh[i]) atomicAdd(&g_counts[i], sh[i]);
    __threadfence();
    __syncthreads();
    __shared__ int s_last;
    if (tid == 0) s_last = (atomicAdd(&g_done, 1) == HIST_BLKS - 1);
    __syncthreads();
    if (!s_last) return;
    // ---- exclusive scan of g_counts -> rowptr/cursor ----
    __threadfence();
    int base = tid * 8;
    int local[8];
    int sum = 0;
    #pragma unroll
    for (int k = 0; k < 8; k++) {
        int v = (base + k < NR) ? g_counts[base + k] : 0;
        local[k] = sum;
        sum += v;
    }
    int lane = tid & 31, w = tid >> 5;
    int v = sum;
    #pragma unroll
    for (int o = 1; o < 32; o <<= 1) {
        int n = __shfl_up_sync(0xffffffffu, v, o);
        if (lane >= o) v += n;
    }
    __shared__ int wsum[8];
    if (lane == 31) wsum[w] = v;
    __syncthreads();
    int add = 0;
    for (int i = 0; i < w; i++) add += wsum[i];
    int incl = v + add;
    int excl = incl - sum;
    #pragma unroll
    for (int k = 0; k < 8; k++) {
        int pos = base + k;
        if (pos < NR) {
            int p = excl + local[k];
            g_rowptr[pos] = p;
            g_cursor[pos] = p;
        }
    }
    if (tid == 255) g_rowptr[NR] = incl;
}

// ---------------- scatter: two-phase smem counting ----------------
#define SCAT_BLKS 120
#define SCAT_CHUNK (NE / SCAT_BLKS)  // 5000
__global__ void scatter_kernel(const int* __restrict__ oi, const int* __restrict__ ri) {
    __shared__ int cnt[NR], base[NR];
    int tid = threadIdx.x;  // 512
    int lo = blockIdx.x * SCAT_CHUNK, hi = lo + SCAT_CHUNK;
    for (int i = tid; i < NR; i += 512) cnt[i] = 0;
    __syncthreads();
    for (int e = lo + tid; e < hi; e += 512) atomicAdd(&cnt[ri[e]], 1);
    __syncthreads();
    for (int i = tid; i < NR; i += 512) {
        int c = cnt[i];
        base[i] = c ? atomicAdd(&g_cursor[i], c) : 0;
        cnt[i] = 0;
    }
    __syncthreads();
    for (int e = lo + tid; e < hi; e += 512) {
        int rr = ri[e];
        int pos = base[rr] + atomicAdd(&cnt[rr], 1);
        g_edge[pos] = make_int2(oi[e], e);
    }
}

// ---------------- aggregation: one rider per 256-thread block ----------------
// Phase A: each lane computes one edge's weight. Phase B: broadcast (w,oi),
// whole warp accumulates the feature row (LDG.64 + cvt + 4 FFMA per edge).
template <int LAYER>
__global__ void __launch_bounds__(256) agg_kernel() {
    int r = blockIdx.x;
    int tid = threadIdx.x, warp = tid >> 5, lane = tid & 31;
    int start = g_rowptr[r], end = g_rowptr[r + 1];
    float adr = (LAYER == 1) ? g_ad1[r] : g_ad2[r];
    const uint2* xh = reinterpret_cast<const uint2*>((LAYER == 1) ? g_xh : g_xhr) + lane;

    float4 acc = make_float4(0.f, 0.f, 0.f, 0.f);
    float sumw = 0.f;
    for (int cb = start + warp * 32; cb < end; cb += 256) {
        int idx = cb + lane;
        int oi_l = 0;
        float w_l = 0.f;
        if (idx < end) {
            int2 e = g_edge[idx];
            oi_l = e.x;
            float2 as = g_as12[e.x];
            float a = (LAYER == 1) ? as.x : as.y;
            w_l = __expf(lrelu(a + adr));
        }
        sumw += w_l;
        int n = min(32, end - cb);
        #pragma unroll 4
        for (int k = 0; k < n; k++) {
            float wk = __shfl_sync(0xffffffffu, w_l, k);
            int ok = __shfl_sync(0xffffffffu, oi_l, k);
            uint2 u = xh[ok * 32];
            float2 f01 = __half22float2(*reinterpret_cast<__half2*>(&u.x));
            float2 f23 = __half22float2(*reinterpret_cast<__half2*>(&u.y));
            acc.x += wk * f01.x;
            acc.y += wk * f01.y;
            acc.z += wk * f23.x;
            acc.w += wk * f23.y;
        }
    }
    __shared__ float4 s_acc[8][32];
    __shared__ float s_w[8];
    #pragma unroll
    for (int o = 16; o; o >>= 1) sumw += __shfl_down_sync(0xffffffffu, sumw, o);
    s_acc[warp][lane] = acc;
    if (lane == 0) s_w[warp] = sumw;
    __syncthreads();
    if (tid < 128) {
        float tot = s_w[0] + s_w[1] + s_w[2] + s_w[3] + s_w[4] + s_w[5] + s_w[6] + s_w[7];
        const float* sf = reinterpret_cast<const float*>(s_acc);
        float a = 0.f;
        #pragma unroll
        for (int w = 0; w < 8; w++) a += sf[w * 128 + tid];
        g_agg[r * 128 + tid] = a / (tot + 1e-16f);
    }
}

// ---------------- gemm + ad2 epilogue: ad2 = relu(agg@Ws1+b1)·vd2 ----------------
__global__ void gemm_ad2(const float* __restrict__ Ws1, const float* __restrict__ b1) {
    __shared__ float Ws[32 * 128];
    __shared__ float As[16 * 128];
    __shared__ float Os[16 * 128];
    int tid = threadIdx.x;  // 128
    int r0 = blockIdx.x * 16;
    for (int i = tid; i < 16 * 128; i += 128) As[i] = g_agg[r0 * 128 + i];
    float acc[16];
    #pragma unroll
    for (int i = 0; i < 16; i++) acc[i] = 0.f;
    for (int kk = 0; kk < 4; kk++) {
        __syncthreads();
        for (int i = tid; i < 32 * 128; i += 128) Ws[i] = Ws1[kk * 32 * 128 + i];
        __syncthreads();
        #pragma unroll 8
        for (int k = 0; k < 32; k++) {
            float wv = Ws[k * 128 + tid];
            #pragma unroll
            for (int i = 0; i < 16; i++) acc[i] += As[i * 128 + kk * 32 + k] * wv;
        }
    }
    float bv = b1[tid], vt = g_vd2[tid];
    #pragma unroll
    for (int i = 0; i < 16; i++) Os[i * 128 + tid] = fmaxf(acc[i] + bv, 0.f) * vt;
    __syncthreads();
    int warp = tid >> 5, lane = tid & 31;
    for (int i = warp; i < 16; i += 4) {
        float s = Os[i * 128 + lane] + Os[i * 128 + 32 + lane] +
                  Os[i * 128 + 64 + lane] + Os[i * 128 + 96 + lane];
        #pragma unroll
        for (int o = 16; o; o >>= 1) s += __shfl_down_sync(0xffffffffu, s, o);
        if (lane == 0) g_ad2[r0 + i] = s;
    }
}

// ---------------- gemm r2 = agg@Ws2 + b2 ----------------
__global__ void gemm_r2(const float* __restrict__ Ws2, const float* __restrict__ b2) {
    __shared__ float Ws[32 * 128];
    __shared__ float As[16 * 128];
    int tid = threadIdx.x;  // 128
    int r0 = blockIdx.x * 16;
    for (int i = tid; i < 16 * 128; i += 128) As[i] = g_agg[r0 * 128 + i];
    float acc[16];
    #pragma unroll
    for (int i = 0; i < 16; i++) acc[i] = 0.f;
    for (int kk = 0; kk < 4; kk++) {
        __syncthreads();
        for (int i = tid; i < 32 * 128; i += 128) Ws[i] = Ws2[kk * 32 * 128 + i];
        __syncthreads();
        #pragma unroll 8
        for (int k = 0; k < 32; k++) {
            float wv = Ws[k * 128 + tid];
            #pragma unroll
            for (int i = 0; i < 16; i++) acc[i] += As[i * 128 + kk * 32 + k] * wv;
        }
    }
    float bv = b2[tid];
    #pragma unroll
    for (int i = 0; i < 16; i++) g_r2[(r0 + i) * 128 + tid] = acc[i] + bv;
}

// ---------------- scoring: block per rider, butterfly-reduced dot per edge ----------------
__global__ void __launch_bounds__(256) score_kernel(float* __restrict__ out) {
    int r = blockIdx.x;
    int warp = threadIdx.x >> 5, lane = threadIdx.x & 31;
    int start = g_rowptr[r], end = g_rowptr[r + 1];
    float4 rv = ((const float4*)(g_r2 + r * 128))[lane];
    const uint2* xh = reinterpret_cast<const uint2*>(g_xhr) + lane;
    for (int cb = start + warp * 32; cb < end; cb += 256) {
        int idx = cb + lane;
        int2 e = (idx < end) ? g_edge[idx] : make_int2(0, 0);
        int n = min(32, end - cb);
        #pragma unroll 4
        for (int k = 0; k < n; k++) {
            int ok = __shfl_sync(0xffffffffu, e.x, k);
            uint2 u = xh[ok * 32];
            float2 f01 = __half22float2(*reinterpret_cast<__half2*>(&u.x));
            float2 f23 = __half22float2(*reinterpret_cast<__half2*>(&u.y));
            float s = f01.x * rv.x + f01.y * rv.y + f23.x * rv.z + f23.y * rv.w;
            #pragma unroll
            for (int o = 16; o; o >>= 1) s += __shfl_xor_sync(0xffffffffu, s, o);
            if (lane == k) out[e.y] = 1.f / (1.f + __expf(-s));
        }
    }
}

// ---------------- launch ----------------
extern "C" void kernel_launch(void* const* d_in, const int* in_sizes, int n_in,
                              void* d_out, int out_size) {
    const float* x_order   = (const float*)d_in[0];
    const float* x_rider   = (const float*)d_in[1];
    const int*   order_idx = (const int*)d_in[2];
    const int*   rider_idx = (const int*)d_in[3];
    const float* Ws1 = (const float*)d_in[4];
    const float* Wd1 = (const float*)d_in[5];
    const float* as1 = (const float*)d_in[6];
    const float* ad1 = (const float*)d_in[7];
    const float* b1  = (const float*)d_in[8];
    const float* Ws2 = (const float*)d_in[9];
    const float* Wd2 = (const float*)d_in[10];
    const float* as2 = (const float*)d_in[11];
    const float* ad2 = (const float*)d_in[12];
    const float* b2  = (const float*)d_in[13];
    float* out = (float*)d_out;

    prep_kernel<<<254, 256>>>(x_rider, Ws1, as1, Wd1, ad1, Ws2, as2, Wd2, ad2);
    convert_hist_scan<<<CONV_BLKS + HIST_BLKS, 256>>>(x_order, rider_idx);
    scatter_kernel<<<SCAT_BLKS, 512>>>(order_idx, rider_idx);
    agg_kernel<1><<<NR, 256>>>();
    gemm_ad2<<<NR / 16, 128>>>(Ws1, b1);
    agg_kernel<2><<<NR, 256>>>();
    gemm_r2<<<NR / 16, 128>>>(Ws2, b2);
    score_kernel<<<NR, 256>>>(out);
}

// round 10
// speedup vs baseline: 1.1227x; 1.1227x over previous
#include <cuda_runtime.h>
#include <cuda_fp16.h>
#include <math.h>

#define NO 50000
#define NR 2000
#define NE 600000
#define D  128
#define NEG_SLOPE 0.2f

// ---------------- scratch ----------------
__device__ float  g_v1[D], g_v2[D], g_vd2[D];
__device__ float  g_ad1[NR], g_ad2[NR];
__device__ float2 g_as12[NO];
__device__ int    g_counts[NR];
__device__ int    g_rowptr[NR + 1];
__device__ int    g_cursor[NR];
__device__ int    g_done;
__device__ int2   g_edge[NE];          // (order_idx, edge_id) CSR order
__device__ __half g_xh[NO * D];        // fp16 x_order (raw)      12.8MB
__device__ __half g_xhr[NO * D];       // fp16 relu(x_order)      12.8MB
__device__ float  g_agg[NR * D];
__device__ float  g_r2[NR * D];

__device__ __forceinline__ float lrelu(float x) { return fmaxf(x, NEG_SLOPE * x); }

// ---------------- prep: v-vectors, ad1 rowdots, zero counters ----------------
__global__ void prep_kernel(const float* __restrict__ xr,
                            const float* __restrict__ Ws1, const float* __restrict__ as1v,
                            const float* __restrict__ Wd1, const float* __restrict__ ad1v,
                            const float* __restrict__ Ws2, const float* __restrict__ as2v,
                            const float* __restrict__ Wd2, const float* __restrict__ ad2v) {
    int b = blockIdx.x, t = threadIdx.x;  // 256 threads
    if (b < 250) {
        __shared__ __align__(16) float vd1[128];
        if (t < 128) {
            float s = 0.f;
            #pragma unroll 8
            for (int d = 0; d < 128; d++) s += Wd1[t * 128 + d] * ad1v[d];
            vd1[t] = s;
        }
        __syncthreads();
        int warp = t >> 5, lane = t & 31;
        int r = b * 8 + warp;
        float4 xv = ((const float4*)xr)[r * 32 + lane];
        float4 vv = ((const float4*)vd1)[lane];
        float s = xv.x * vv.x + xv.y * vv.y + xv.z * vv.z + xv.w * vv.w;
        #pragma unroll
        for (int o = 16; o; o >>= 1) s += __shfl_down_sync(0xffffffffu, s, o);
        if (lane == 0) g_ad1[r] = s;
    } else if (b == 253) {
        for (int i = t; i < NR; i += 256) g_counts[i] = 0;
        if (t == 0) g_done = 0;
    } else if (t < 128) {
        const float *W, *a;
        float* v;
        if (b == 250)      { W = Ws1; a = as1v; v = g_v1; }
        else if (b == 251) { W = Ws2; a = as2v; v = g_v2; }
        else               { W = Wd2; a = ad2v; v = g_vd2; }
        float s = 0.f;
        #pragma unroll 8
        for (int d = 0; d < 128; d++) s += W[t * 128 + d] * a[d];
        v[t] = s;
    }
}

// ---------------- convert (raw + relu copies) + hist + (last block) scan ----------------
#define CONV_BLKS (NO / 8)           // 6250
#define HIST_BLKS 60
#define HIST_CHUNK (NE / HIST_BLKS)  // 10000
__global__ void convert_hist_scan(const float* __restrict__ x, const int* __restrict__ ri) {
    if (blockIdx.x < CONV_BLKS) {
        int row = blockIdx.x * 8 + (threadIdx.x >> 5);
        int lane = threadIdx.x & 31;
        float4 xv = ((const float4*)x)[row * 32 + lane];
        uint2 u, ur;
        *reinterpret_cast<__half2*>(&u.x) = __floats2half2_rn(xv.x, xv.y);
        *reinterpret_cast<__half2*>(&u.y) = __floats2half2_rn(xv.z, xv.w);
        *reinterpret_cast<__half2*>(&ur.x) = __floats2half2_rn(fmaxf(xv.x, 0.f), fmaxf(xv.y, 0.f));
        *reinterpret_cast<__half2*>(&ur.y) = __floats2half2_rn(fmaxf(xv.z, 0.f), fmaxf(xv.w, 0.f));
        reinterpret_cast<uint2*>(g_xh)[row * 32 + lane] = u;
        reinterpret_cast<uint2*>(g_xhr)[row * 32 + lane] = ur;
        float4 v1 = ((const float4*)g_v1)[lane];
        float4 v2 = ((const float4*)g_v2)[lane];
        float s1 = xv.x * v1.x + xv.y * v1.y + xv.z * v1.z + xv.w * v1.w;
        float s2 = fmaxf(xv.x, 0.f) * v2.x + fmaxf(xv.y, 0.f) * v2.y +
                   fmaxf(xv.z, 0.f) * v2.z + fmaxf(xv.w, 0.f) * v2.w;
        #pragma unroll
        for (int o = 16; o; o >>= 1) {
            s1 += __shfl_down_sync(0xffffffffu, s1, o);
            s2 += __shfl_down_sync(0xffffffffu, s2, o);
        }
        if (lane == 0) g_as12[row] = make_float2(s1, s2);
        return;
    }
    // ---- histogram blocks ----
    __shared__ int sh[NR];
    int tid = threadIdx.x;
    int b = blockIdx.x - CONV_BLKS;
    int lo = b * HIST_CHUNK, hi = lo + HIST_CHUNK;
    for (int i = tid; i < NR; i += blockDim.x) sh[i] = 0;
    __syncthreads();
    for (int e = lo + tid; e < hi; e += blockDim.x) atomicAdd(&sh[ri[e]], 1);
    __syncthreads();
    for (int i = tid; i < NR; i += blockDim.x)
        if (sh[i]) atomicAdd(&g_counts[i], sh[i]);
    __threadfence();
    __syncthreads();
    __shared__ int s_last;
    if (tid == 0) s_last = (atomicAdd(&g_done, 1) == HIST_BLKS - 1);
    __syncthreads();
    if (!s_last) return;
    // ---- exclusive scan of g_counts -> rowptr/cursor ----
    __threadfence();
    int base = tid * 8;
    int local[8];
    int sum = 0;
    #pragma unroll
    for (int k = 0; k < 8; k++) {
        int v = (base + k < NR) ? g_counts[base + k] : 0;
        local[k] = sum;
        sum += v;
    }
    int lane = tid & 31, w = tid >> 5;
    int v = sum;
    #pragma unroll
    for (int o = 1; o < 32; o <<= 1) {
        int n = __shfl_up_sync(0xffffffffu, v, o);
        if (lane >= o) v += n;
    }
    __shared__ int wsum[8];
    if (lane == 31) wsum[w] = v;
    __syncthreads();
    int add = 0;
    for (int i = 0; i < w; i++) add += wsum[i];
    int incl = v + add;
    int excl = incl - sum;
    #pragma unroll
    for (int k = 0; k < 8; k++) {
        int pos = base + k;
        if (pos < NR) {
            int p = excl + local[k];
            g_rowptr[pos] = p;
            g_cursor[pos] = p;
        }
    }
    if (tid == 255) g_rowptr[NR] = incl;
}

// ---------------- scatter: two-phase smem counting ----------------
#define SCAT_BLKS 120
#define SCAT_CHUNK (NE / SCAT_BLKS)  // 5000
__global__ void scatter_kernel(const int* __restrict__ oi, const int* __restrict__ ri) {
    __shared__ int cnt[NR], base[NR];
    int tid = threadIdx.x;  // 512
    int lo = blockIdx.x * SCAT_CHUNK, hi = lo + SCAT_CHUNK;
    for (int i = tid; i < NR; i += 512) cnt[i] = 0;
    __syncthreads();
    for (int e = lo + tid; e < hi; e += 512) atomicAdd(&cnt[ri[e]], 1);
    __syncthreads();
    for (int i = tid; i < NR; i += 512) {
        int c = cnt[i];
        base[i] = c ? atomicAdd(&g_cursor[i], c) : 0;
        cnt[i] = 0;
    }
    __syncthreads();
    for (int e = lo + tid; e < hi; e += 512) {
        int rr = ri[e];
        int pos = base[rr] + atomicAdd(&cnt[rr], 1);
        g_edge[pos] = make_int2(oi[e], e);
    }
}

// ---------------- aggregation: one rider per 256-thread block ----------------
// Phase A: thread-per-edge weight computation -> smem stage (no SHFL!).
// Phase B: warp-per-32-edge slice, LDS broadcast (w,oi) + LDG.64 feature + 4 FFMA.
template <int LAYER>
__global__ void __launch_bounds__(256) agg_kernel() {
    int r = blockIdx.x;
    int tid = threadIdx.x, warp = tid >> 5, lane = tid & 31;
    int start = g_rowptr[r], end = g_rowptr[r + 1];
    float adr = (LAYER == 1) ? g_ad1[r] : g_ad2[r];
    const uint2* xh = reinterpret_cast<const uint2*>((LAYER == 1) ? g_xh : g_xhr) + lane;

    __shared__ float sw[256];
    __shared__ int   soi[256];
    __shared__ float4 s_acc[8][32];
    __shared__ float  s_wsum[8];

    float4 acc = make_float4(0.f, 0.f, 0.f, 0.f);
    float sumw = 0.f;
    for (int cb = start; cb < end; cb += 256) {
        // phase A
        int idx = cb + tid;
        float w = 0.f;
        int oi = 0;
        if (idx < end) {
            int2 e = g_edge[idx];
            oi = e.x;
            float2 as = g_as12[e.x];
            float a = (LAYER == 1) ? as.x : as.y;
            w = __expf(lrelu(a + adr));
        }
        sw[tid] = w;
        soi[tid] = oi;
        sumw += w;
        __syncthreads();
        // phase B
        int base = warp * 32;
        int n = min(end - cb - base, 32);
        #pragma unroll 4
        for (int k = 0; k < n; k++) {
            float wk = sw[base + k];
            int ok = soi[base + k];
            uint2 u = xh[ok * 32];
            float2 f01 = __half22float2(*reinterpret_cast<__half2*>(&u.x));
            float2 f23 = __half22float2(*reinterpret_cast<__half2*>(&u.y));
            acc.x += wk * f01.x;
            acc.y += wk * f01.y;
            acc.z += wk * f23.x;
            acc.w += wk * f23.y;
        }
        __syncthreads();
    }
    #pragma unroll
    for (int o = 16; o; o >>= 1) sumw += __shfl_down_sync(0xffffffffu, sumw, o);
    s_acc[warp][lane] = acc;
    if (lane == 0) s_wsum[warp] = sumw;
    __syncthreads();
    if (tid < 128) {
        float tot = s_wsum[0] + s_wsum[1] + s_wsum[2] + s_wsum[3] +
                    s_wsum[4] + s_wsum[5] + s_wsum[6] + s_wsum[7];
        const float* sf = reinterpret_cast<const float*>(s_acc);
        float a = 0.f;
        #pragma unroll
        for (int w = 0; w < 8; w++) a += sf[w * 128 + tid];
        g_agg[r * 128 + tid] = a / (tot + 1e-16f);
    }
}

// ---------------- gemm + ad2 epilogue: ad2 = relu(agg@Ws1+b1)·vd2 ----------------
__global__ void gemm_ad2(const float* __restrict__ Ws1, const float* __restrict__ b1) {
    __shared__ float Ws[32 * 128];
    __shared__ float As[16 * 128];
    __shared__ float Os[16 * 128];
    int tid = threadIdx.x;  // 128
    int r0 = blockIdx.x * 16;
    for (int i = tid; i < 16 * 128; i += 128) As[i] = g_agg[r0 * 128 + i];
    float acc[16];
    #pragma unroll
    for (int i = 0; i < 16; i++) acc[i] = 0.f;
    for (int kk = 0; kk < 4; kk++) {
        __syncthreads();
        for (int i = tid; i < 32 * 128; i += 128) Ws[i] = Ws1[kk * 32 * 128 + i];
        __syncthreads();
        #pragma unroll 8
        for (int k = 0; k < 32; k++) {
            float wv = Ws[k * 128 + tid];
            #pragma unroll
            for (int i = 0; i < 16; i++) acc[i] += As[i * 128 + kk * 32 + k] * wv;
        }
    }
    float bv = b1[tid], vt = g_vd2[tid];
    #pragma unroll
    for (int i = 0; i < 16; i++) Os[i * 128 + tid] = fmaxf(acc[i] + bv, 0.f) * vt;
    __syncthreads();
    int warp = tid >> 5, lane = tid & 31;
    for (int i = warp; i < 16; i += 4) {
        float s = Os[i * 128 + lane] + Os[i * 128 + 32 + lane] +
                  Os[i * 128 + 64 + lane] + Os[i * 128 + 96 + lane];
        #pragma unroll
        for (int o = 16; o; o >>= 1) s += __shfl_down_sync(0xffffffffu, s, o);
        if (lane == 0) g_ad2[r0 + i] = s;
    }
}

// ---------------- gemm r2 = agg@Ws2 + b2 ----------------
__global__ void gemm_r2(const float* __restrict__ Ws2, const float* __restrict__ b2) {
    __shared__ float Ws[32 * 128];
    __shared__ float As[16 * 128];
    int tid = threadIdx.x;  // 128
    int r0 = blockIdx.x * 16;
    for (int i = tid; i < 16 * 128; i += 128) As[i] = g_agg[r0 * 128 + i];
    float acc[16];
    #pragma unroll
    for (int i = 0; i < 16; i++) acc[i] = 0.f;
    for (int kk = 0; kk < 4; kk++) {
        __syncthreads();
        for (int i = tid; i < 32 * 128; i += 128) Ws[i] = Ws2[kk * 32 * 128 + i];
        __syncthreads();
        #pragma unroll 8
        for (int k = 0; k < 32; k++) {
            float wv = Ws[k * 128 + tid];
            #pragma unroll
            for (int i = 0; i < 16; i++) acc[i] += As[i * 128 + kk * 32 + k] * wv;
        }
    }
    float bv = b2[tid];
    #pragma unroll
    for (int i = 0; i < 16; i++) g_r2[(r0 + i) * 128 + tid] = acc[i] + bv;
}

// ---------------- scoring: block per rider, 2-edge unroll + butterfly (R6 form, xhr) ----------------
__global__ void __launch_bounds__(256) score_kernel(float* __restrict__ out) {
    int r = blockIdx.x;
    int warp = threadIdx.x >> 5, lane = threadIdx.x & 31;
    int start = g_rowptr[r], end = g_rowptr[r + 1];
    float4 rv = ((const float4*)(g_r2 + r * 128))[lane];
    const uint2* xh = reinterpret_cast<const uint2*>(g_xhr) + lane;
    for (int j = start + warp * 2; j < end; j += 16) {
        int2 e1 = g_edge[j];
        bool h2 = (j + 1) < end;
        int2 e2 = h2 ? g_edge[j + 1] : e1;
        uint2 u1 = xh[e1.x * 32];
        uint2 u2 = xh[e2.x * 32];
        float2 f01 = __half22float2(*reinterpret_cast<__half2*>(&u1.x));
        float2 f23 = __half22float2(*reinterpret_cast<__half2*>(&u1.y));
        float2 g01 = __half22float2(*reinterpret_cast<__half2*>(&u2.x));
        float2 g23 = __half22float2(*reinterpret_cast<__half2*>(&u2.y));
        float s1 = f01.x * rv.x + f01.y * rv.y + f23.x * rv.z + f23.y * rv.w;
        float s2 = g01.x * rv.x + g01.y * rv.y + g23.x * rv.z + g23.y * rv.w;
        #pragma unroll
        for (int o = 16; o; o >>= 1) {
            s1 += __shfl_down_sync(0xffffffffu, s1, o);
            s2 += __shfl_down_sync(0xffffffffu, s2, o);
        }
        if (lane == 0) {
            out[e1.y] = 1.f / (1.f + __expf(-s1));
            if (h2) out[e2.y] = 1.f / (1.f + __expf(-s2));
        }
    }
}

// ---------------- launch ----------------
extern "C" void kernel_launch(void* const* d_in, const int* in_sizes, int n_in,
                              void* d_out, int out_size) {
    const float* x_order   = (const float*)d_in[0];
    const float* x_rider   = (const float*)d_in[1];
    const int*   order_idx = (const int*)d_in[2];
    const int*   rider_idx = (const int*)d_in[3];
    const float* Ws1 = (const float*)d_in[4];
    const float* Wd1 = (const float*)d_in[5];
    const float* as1 = (const float*)d_in[6];
    const float* ad1 = (const float*)d_in[7];
    const float* b1  = (const float*)d_in[8];
    const float* Ws2 = (const float*)d_in[9];
    const float* Wd2 = (const float*)d_in[10];
    const float* as2 = (const float*)d_in[11];
    const float* ad2 = (const float*)d_in[12];
    const float* b2  = (const float*)d_in[13];
    float* out = (float*)d_out;

    prep_kernel<<<254, 256>>>(x_rider, Ws1, as1, Wd1, ad1, Ws2, as2, Wd2, ad2);
    convert_hist_scan<<<CONV_BLKS + HIST_BLKS, 256>>>(x_order, rider_idx);
    scatter_kernel<<<SCAT_BLKS, 512>>>(order_idx, rider_idx);
    agg_kernel<1><<<NR, 256>>>();
    gemm_ad2<<<NR / 16, 128>>>(Ws1, b1);
    agg_kernel<2><<<NR, 256>>>();
    gemm_r2<<<NR / 16, 128>>>(Ws2, b2);
    score_kernel<<<NR, 256>>>(out);
}